// round 2
// baseline (speedup 1.0000x reference)
#include <cuda_runtime.h>
#include <cstdint>
#include <math.h>

// Problem constants
#define TT   8192
#define DD   1024
#define EE   8
#define FFD  3584

// GEMM tiling
#define BM   128
#define BN   64
#define BK   32
#define PADK 36     // 36-float row stride: 144B, 16B-aligned, conflict-free frag loads
#define NSTAGE 3    // cp.async pipeline depth

#define MPMAX  (2*TT + EE*BM)   // 17408 max padded slot rows
#define MTILES (MPMAX/BM)       // 136

// ---------------- scratch (device globals; no allocation allowed) ----------------
__device__ float g_xg[(size_t)MPMAX * DD];    // gathered tf32-rounded x  (68 MB)
__device__ float g_h [(size_t)MPMAX * FFD];   // silu(G)*U, tf32-rounded (250 MB)
__device__ float g_y [(size_t)MPMAX * DD];    // per-slot expert output   (68 MB)
__device__ int   g_perm[MPMAX];               // slot -> token (-1 = pad)
__device__ int   g_ridx[TT * 2];              // token -> (expert0, expert1)
__device__ float g_rw  [TT * 2];              // token -> (w0, w1)
__device__ int   g_slot[TT * 2];              // token -> (slot0, slot1)
__device__ int   g_cnt [EE];
__device__ int   g_poff[EE + 1];              // padded segment offsets

// ---------------- small helpers ----------------
__device__ __forceinline__ uint32_t cvt_tf32_bits(float v) {
    uint32_t r;
    asm("cvt.rna.tf32.f32 %0, %1;" : "=r"(r) : "f"(v));
    return r;
}
__device__ __forceinline__ float tf32f(float v) {
    return __uint_as_float(cvt_tf32_bits(v));
}
__device__ __forceinline__ void cp16(uint32_t saddr, const float* gptr) {
    asm volatile("cp.async.ca.shared.global [%0], [%1], 16;" :: "r"(saddr), "l"(gptr));
}
__device__ __forceinline__ void cp_commit() {
    asm volatile("cp.async.commit_group;" ::: "memory");
}
__device__ __forceinline__ void mma8(float (&d)[4], const uint32_t (&a)[4], const uint32_t (&b)[2]) {
    asm volatile(
        "mma.sync.aligned.m16n8k8.row.col.f32.tf32.tf32.f32 "
        "{%0,%1,%2,%3},{%4,%5,%6,%7},{%8,%9},{%0,%1,%2,%3};"
        : "+f"(d[0]), "+f"(d[1]), "+f"(d[2]), "+f"(d[3])
        : "r"(a[0]), "r"(a[1]), "r"(a[2]), "r"(a[3]), "r"(b[0]), "r"(b[1]));
}
__device__ __forceinline__ float silu_mul(float gv, float uv) {
    return (gv / (1.0f + __expf(-gv))) * uv;
}

// ---------------- routing: softmax-top2 == softmax over the top-2 logits ----------------
__global__ void k_route(const float* __restrict__ logits) {
    int t = blockIdx.x * blockDim.x + threadIdx.x;
    if (t >= TT) return;
    float v[EE];
#pragma unroll
    for (int e = 0; e < EE; e++) v[e] = logits[t * EE + e];
    int i0 = 0; float b0 = v[0];
#pragma unroll
    for (int e = 1; e < EE; e++) if (v[e] > b0) { b0 = v[e]; i0 = e; }
    int i1 = -1; float b1 = -INFINITY;
#pragma unroll
    for (int e = 0; e < EE; e++) if (e != i0 && v[e] > b1) { b1 = v[e]; i1 = e; }
    float w0 = 1.0f / (1.0f + __expf(b1 - b0));   // = p0/(p0+p1) after renorm
    g_ridx[2 * t] = i0;  g_ridx[2 * t + 1] = i1;
    g_rw  [2 * t] = w0;  g_rw  [2 * t + 1] = 1.0f - w0;
}

__global__ void k_count() {
    int e = blockIdx.x, tid = threadIdx.x;
    __shared__ int red[256];
    int s = 0;
    for (int t = tid; t < TT; t += 256)
        s += (g_ridx[2 * t] == e) + (g_ridx[2 * t + 1] == e);
    red[tid] = s; __syncthreads();
    for (int o = 128; o > 0; o >>= 1) {
        if (tid < o) red[tid] += red[tid + o];
        __syncthreads();
    }
    if (tid == 0) g_cnt[e] = red[0];
}

__global__ void k_offsets() {
    int acc = 0;
    g_poff[0] = 0;
    for (int e = 0; e < EE; e++) {
        acc += ((g_cnt[e] + BM - 1) / BM) * BM;
        g_poff[e + 1] = acc;
    }
}

// stable (token-order) scatter of tokens into per-expert segments; deterministic
__global__ void k_scatter() {
    int e = blockIdx.x, tid = threadIdx.x;
    __shared__ int s[256];
    __shared__ int base;
    if (tid == 0) base = 0;
    __syncthreads();
    int off = g_poff[e];
    for (int b = 0; b < TT; b += 256) {
        int t = b + tid;
        int which = -1;
        if (g_ridx[2 * t] == e) which = 0;
        else if (g_ridx[2 * t + 1] == e) which = 1;
        int act = (which >= 0) ? 1 : 0;
        s[tid] = act; __syncthreads();
        // inclusive Hillis-Steele scan
        for (int o = 1; o < 256; o <<= 1) {
            int v = (tid >= o) ? s[tid - o] : 0;
            __syncthreads();
            s[tid] += v;
            __syncthreads();
        }
        if (act) {
            int pos = base + s[tid] - 1;
            g_perm[off + pos] = t;
            g_slot[2 * t + which] = off + pos;
        }
        __syncthreads();
        if (tid == 0) base += s[255];
        __syncthreads();
    }
    // mark pad tail of the segment
    int cnt = g_cnt[e];
    for (int p = off + cnt + tid; p < g_poff[e + 1]; p += 256) g_perm[p] = -1;
}

// gather x rows into slot order, rounded to tf32 (round-to-nearest!)
__global__ void k_gather(const float* __restrict__ x) {
    int row = blockIdx.x;
    if (row >= g_poff[EE]) return;
    int t = g_perm[row];
    int i = threadIdx.x;                 // 256 threads, DD/4 = 256 float4
    float4 v = make_float4(0.f, 0.f, 0.f, 0.f);
    if (t >= 0) {
        v = reinterpret_cast<const float4*>(x + (size_t)t * DD)[i];
        v.x = tf32f(v.x); v.y = tf32f(v.y); v.z = tf32f(v.z); v.w = tf32f(v.w);
    }
    reinterpret_cast<float4*>(g_xg + (size_t)row * DD)[i] = v;
}

// ---------------- grouped GEMM (mma.sync m16n8k8 tf32, cp.async NSTAGE pipeline) --------
// FUSED=true : A=g_xg [M,1024], B1=w1, B3=w3 (each expert [F,1024]); C=g_h (silu(G)*U, tf32)
// FUSED=false: A=g_h  [M,3584], B1=w2 (each expert [D,3584]);        C=g_y (raw fp32)
template<int KD, bool FUSED>
__global__ void __launch_bounds__(256)
k_gemm(const float* __restrict__ B1g, const float* __restrict__ B3g) {
    constexpr int NB    = FUSED ? 2 : 1;
    constexpr int STAGE = (BM + NB * BN) * PADK;   // floats per stage
    constexpr int NK    = KD / BK;
    constexpr int NROWS = FUSED ? FFD : DD;        // B rows per expert

    extern __shared__ float smem[];

    int m0 = blockIdx.y * BM;
    if (m0 >= g_poff[EE]) return;
    int e = 0;
#pragma unroll
    for (int i = 1; i < EE; i++) if (m0 >= g_poff[i]) e = i;

    int n0 = blockIdx.x * BN;
    const float* Ap  = (FUSED ? g_xg : g_h) + (size_t)m0 * KD;
    const float* B1p = B1g + (size_t)e * NROWS * KD + (size_t)n0 * KD;
    const float* B3p = FUSED ? (B3g + (size_t)e * FFD * KD + (size_t)n0 * KD) : nullptr;

    uint32_t sbase = (uint32_t)__cvta_generic_to_shared(smem);
    int tid = threadIdx.x;

    auto load_stage = [&](int kt, int buf) {
        uint32_t sb = sbase + (uint32_t)buf * STAGE * 4;
        int k0 = kt * BK;
#pragma unroll
        for (int c = 0; c < 4; c++) {               // A: 128x32 = 1024 x 16B chunks
            int ch = tid + c * 256;
            int row = ch >> 3, kc = (ch & 7) * 4;
            cp16(sb + (uint32_t)(row * PADK + kc) * 4, Ap + (size_t)row * KD + k0 + kc);
        }
#pragma unroll
        for (int c = 0; c < 2; c++) {               // each B: 64x32 = 512 x 16B chunks
            int ch = tid + c * 256;
            int row = ch >> 3, kc = (ch & 7) * 4;
            cp16(sb + (uint32_t)(BM * PADK + row * PADK + kc) * 4,
                 B1p + (size_t)row * KD + k0 + kc);
            if (FUSED)
                cp16(sb + (uint32_t)((BM + BN) * PADK + row * PADK + kc) * 4,
                     B3p + (size_t)row * KD + k0 + kc);
        }
        cp_commit();
    };

    int warp = tid >> 5, lane = tid & 31;
    int wm = warp >> 1, wn = warp & 1;   // 4x2 warp grid, warp tile 32x32
    int g = lane >> 2, tg = lane & 3;

    float accG[2][4][4];
    float accU[2][4][4];
#pragma unroll
    for (int i = 0; i < 2; i++)
#pragma unroll
        for (int j = 0; j < 4; j++)
#pragma unroll
            for (int l = 0; l < 4; l++) {
                accG[i][j][l] = 0.f;
                if (FUSED) accU[i][j][l] = 0.f;
            }

    // prologue: fill NSTAGE-1 stages
#pragma unroll
    for (int p = 0; p < NSTAGE - 1; p++) load_stage(p, p);

    int buf = 0;
    for (int kt = 0; kt < NK; ++kt) {
        if (kt + NSTAGE - 1 < NK) {
            load_stage(kt + NSTAGE - 1, (buf + NSTAGE - 1) % NSTAGE);
            asm volatile("cp.async.wait_group %0;" :: "n"(NSTAGE - 1) : "memory");
        } else {
            asm volatile("cp.async.wait_group 0;" ::: "memory");
        }
        __syncthreads();

        const float* s   = smem + buf * STAGE;
        const float* sA  = s;
        const float* sB1 = s + BM * PADK;
        const float* sB3 = sB1 + BN * PADK;

#pragma unroll
        for (int ks = 0; ks < BK / 8; ks++) {
            int kk = ks * 8;
            uint32_t a[2][4];
#pragma unroll
            for (int i = 0; i < 2; i++) {
                int r = wm * 32 + i * 16 + g;
                a[i][0] = __float_as_uint(sA[r * PADK + kk + tg]);          // pre-rounded
                a[i][1] = __float_as_uint(sA[(r + 8) * PADK + kk + tg]);
                a[i][2] = __float_as_uint(sA[r * PADK + kk + tg + 4]);
                a[i][3] = __float_as_uint(sA[(r + 8) * PADK + kk + tg + 4]);
            }
#pragma unroll
            for (int j = 0; j < 4; j++) {
                int n = wn * 32 + j * 8 + g;
                uint32_t b1[2];
                b1[0] = cvt_tf32_bits(sB1[n * PADK + kk + tg]);             // RN round!
                b1[1] = cvt_tf32_bits(sB1[n * PADK + kk + tg + 4]);
                mma8(accG[0][j], a[0], b1);
                mma8(accG[1][j], a[1], b1);
                if (FUSED) {
                    uint32_t b3[2];
                    b3[0] = cvt_tf32_bits(sB3[n * PADK + kk + tg]);
                    b3[1] = cvt_tf32_bits(sB3[n * PADK + kk + tg + 4]);
                    mma8(accU[0][j], a[0], b3);
                    mma8(accU[1][j], a[1], b3);
                }
            }
        }
        __syncthreads();
        buf = (buf + 1) % NSTAGE;
    }

    // epilogue
#pragma unroll
    for (int i = 0; i < 2; i++) {
        int r = m0 + wm * 32 + i * 16 + g;
#pragma unroll
        for (int j = 0; j < 4; j++) {
            int c = n0 + wn * 32 + j * 8 + 2 * tg;
            if (FUSED) {
                float h0 = silu_mul(accG[i][j][0], accU[i][j][0]);
                float h1 = silu_mul(accG[i][j][1], accU[i][j][1]);
                float h2 = silu_mul(accG[i][j][2], accU[i][j][2]);
                float h3 = silu_mul(accG[i][j][3], accU[i][j][3]);
                *reinterpret_cast<float2*>(g_h + (size_t)r * FFD + c) =
                    make_float2(tf32f(h0), tf32f(h1));
                *reinterpret_cast<float2*>(g_h + (size_t)(r + 8) * FFD + c) =
                    make_float2(tf32f(h2), tf32f(h3));
            } else {
                *reinterpret_cast<float2*>(g_y + (size_t)r * DD + c) =
                    make_float2(accG[i][j][0], accG[i][j][1]);
                *reinterpret_cast<float2*>(g_y + (size_t)(r + 8) * DD + c) =
                    make_float2(accG[i][j][2], accG[i][j][3]);
            }
        }
    }
}

// final weighted combine: out[t] = w0*Y[slot0] + w1*Y[slot1]  (exactly 2 terms -> deterministic)
__global__ void k_combine(float* __restrict__ out) {
    int t = blockIdx.x;
    int s0 = g_slot[2 * t], s1 = g_slot[2 * t + 1];
    float w0 = g_rw[2 * t], w1v = g_rw[2 * t + 1];
    int i = threadIdx.x;   // 256 threads, one float4 each
    float4 a = reinterpret_cast<const float4*>(g_y + (size_t)s0 * DD)[i];
    float4 b = reinterpret_cast<const float4*>(g_y + (size_t)s1 * DD)[i];
    float4 r;
    r.x = w0 * a.x + w1v * b.x;
    r.y = w0 * a.y + w1v * b.y;
    r.z = w0 * a.z + w1v * b.z;
    r.w = w0 * a.w + w1v * b.w;
    reinterpret_cast<float4*>(out + (size_t)t * DD)[i] = r;
}

// ---------------- launch ----------------
extern "C" void kernel_launch(void* const* d_in, const int* in_sizes, int n_in,
                              void* d_out, int out_size) {
    const float* x      = (const float*)d_in[0];
    const float* w1     = (const float*)d_in[1];
    const float* w3     = (const float*)d_in[2];
    const float* w2     = (const float*)d_in[3];
    const float* logits = (const float*)d_in[4];
    float* out = (float*)d_out;

    constexpr int SMEM1 = NSTAGE * (BM + 2 * BN) * PADK * 4;  // 110592 B
    constexpr int SMEM2 = NSTAGE * (BM + 1 * BN) * PADK * 4;  //  82944 B
    cudaFuncSetAttribute((const void*)k_gemm<DD,  true >,
                         cudaFuncAttributeMaxDynamicSharedMemorySize, SMEM1);
    cudaFuncSetAttribute((const void*)k_gemm<FFD, false>,
                         cudaFuncAttributeMaxDynamicSharedMemorySize, SMEM2);

    k_route  <<<TT / 256, 256>>>(logits);
    k_count  <<<EE, 256>>>();
    k_offsets<<<1, 1>>>();
    k_scatter<<<EE, 256>>>();
    k_gather <<<MPMAX, 256>>>(x);

    k_gemm<DD,  true ><<<dim3(FFD / BN, MTILES), 256, SMEM1>>>(w1, w3);
    k_gemm<FFD, false><<<dim3(DD  / BN, MTILES), 256, SMEM2>>>(w2, nullptr);

    k_combine<<<TT, 256>>>(out);
}

// round 5
// speedup vs baseline: 1.0880x; 1.0880x over previous
#include <cuda_runtime.h>
#include <cstdint>
#include <math.h>

// Problem constants
#define TT   8192
#define DD   1024
#define EE   8
#define FFD  3584

// GEMM tiling
#define BM   128
#define BN   64
#define BK   32
#define PADK 36     // 36-float row stride: 144B, 16B-aligned, conflict-free frag loads
#define NSTAGE 2    // 2 stages + 2 CTAs/SM for latency hiding

#define MPMAX  (2*TT + EE*BM)   // 17408 max padded slot rows
#define MTILES (MPMAX/BM)       // 136

// ---------------- scratch (device globals; no allocation allowed) ----------------
__device__ float g_xg [(size_t)MPMAX * DD];    // gathered tf32-rounded x
__device__ float g_h  [(size_t)MPMAX * FFD];   // silu(G)*U, tf32-rounded
__device__ float g_y  [(size_t)MPMAX * DD];    // per-slot expert output
__device__ float g_w1r[(size_t)EE * FFD * DD]; // RN-rounded weights (hot-loop cvt removal)
__device__ float g_w3r[(size_t)EE * FFD * DD];
__device__ float g_w2r[(size_t)EE * DD * FFD];
__device__ int   g_perm[MPMAX];
__device__ int   g_ridx[TT * 2];
__device__ float g_rw  [TT * 2];
__device__ int   g_slot[TT * 2];
__device__ int   g_cnt [EE];
__device__ int   g_poff[EE + 1];

// ---------------- helpers ----------------
__device__ __forceinline__ uint32_t cvt_tf32_bits(float v) {
    uint32_t r;
    asm("cvt.rna.tf32.f32 %0, %1;" : "=r"(r) : "f"(v));
    return r;
}
__device__ __forceinline__ float tf32f(float v) {
    return __uint_as_float(cvt_tf32_bits(v));
}
__device__ __forceinline__ void cp16(uint32_t saddr, const float* gptr) {
    asm volatile("cp.async.cg.shared.global [%0], [%1], 16;" :: "r"(saddr), "l"(gptr));
}
__device__ __forceinline__ void cp_commit() {
    asm volatile("cp.async.commit_group;" ::: "memory");
}
__device__ __forceinline__ void mma8(float (&d)[4], const uint32_t (&a)[4], const uint32_t (&b)[2]) {
    asm volatile(
        "mma.sync.aligned.m16n8k8.row.col.f32.tf32.tf32.f32 "
        "{%0,%1,%2,%3},{%4,%5,%6,%7},{%8,%9},{%0,%1,%2,%3};"
        : "+f"(d[0]), "+f"(d[1]), "+f"(d[2]), "+f"(d[3])
        : "r"(a[0]), "r"(a[1]), "r"(a[2]), "r"(a[3]), "r"(b[0]), "r"(b[1]));
}
__device__ __forceinline__ float silu_mul(float gv, float uv) {
    return (gv / (1.0f + __expf(-gv))) * uv;
}

// ---------------- routing: softmax-top2 == softmax over the top-2 logits ----------------
__global__ void k_route(const float* __restrict__ logits) {
    int t = blockIdx.x * blockDim.x + threadIdx.x;
    if (t >= TT) return;
    float v[EE];
#pragma unroll
    for (int e = 0; e < EE; e++) v[e] = logits[t * EE + e];
    int i0 = 0; float b0 = v[0];
#pragma unroll
    for (int e = 1; e < EE; e++) if (v[e] > b0) { b0 = v[e]; i0 = e; }
    int i1 = -1; float b1 = -INFINITY;
#pragma unroll
    for (int e = 0; e < EE; e++) if (e != i0 && v[e] > b1) { b1 = v[e]; i1 = e; }
    float w0 = 1.0f / (1.0f + __expf(b1 - b0));
    g_ridx[2 * t] = i0;  g_ridx[2 * t + 1] = i1;
    g_rw  [2 * t] = w0;  g_rw  [2 * t + 1] = 1.0f - w0;
}

__global__ void k_count() {
    int e = blockIdx.x, tid = threadIdx.x;
    __shared__ int red[256];
    int s = 0;
    for (int t = tid; t < TT; t += 256)
        s += (g_ridx[2 * t] == e) + (g_ridx[2 * t + 1] == e);
    red[tid] = s; __syncthreads();
    for (int o = 128; o > 0; o >>= 1) {
        if (tid < o) red[tid] += red[tid + o];
        __syncthreads();
    }
    if (tid == 0) g_cnt[e] = red[0];
}

__global__ void k_offsets() {
    int acc = 0;
    g_poff[0] = 0;
    for (int e = 0; e < EE; e++) {
        acc += ((g_cnt[e] + BM - 1) / BM) * BM;
        g_poff[e + 1] = acc;
    }
}

// stable (token-order) scatter; deterministic
__global__ void k_scatter() {
    int e = blockIdx.x, tid = threadIdx.x;
    __shared__ int s[256];
    __shared__ int base;
    if (tid == 0) base = 0;
    __syncthreads();
    int off = g_poff[e];
    for (int b = 0; b < TT; b += 256) {
        int t = b + tid;
        int which = -1;
        if (g_ridx[2 * t] == e) which = 0;
        else if (g_ridx[2 * t + 1] == e) which = 1;
        int act = (which >= 0) ? 1 : 0;
        s[tid] = act; __syncthreads();
        for (int o = 1; o < 256; o <<= 1) {
            int v = (tid >= o) ? s[tid - o] : 0;
            __syncthreads();
            s[tid] += v;
            __syncthreads();
        }
        if (act) {
            int pos = base + s[tid] - 1;
            g_perm[off + pos] = t;
            g_slot[2 * t + which] = off + pos;
        }
        __syncthreads();
        if (tid == 0) base += s[255];
        __syncthreads();
    }
    int cnt = g_cnt[e];
    for (int p = off + cnt + tid; p < g_poff[e + 1]; p += 256) g_perm[p] = -1;
}

// gather x rows into slot order, RN-rounded to tf32
__global__ void k_gather(const float* __restrict__ x) {
    int row = blockIdx.x;
    if (row >= g_poff[EE]) return;
    int t = g_perm[row];
    int i = threadIdx.x;
    float4 v = make_float4(0.f, 0.f, 0.f, 0.f);
    if (t >= 0) {
        v = reinterpret_cast<const float4*>(x + (size_t)t * DD)[i];
        v.x = tf32f(v.x); v.y = tf32f(v.y); v.z = tf32f(v.z); v.w = tf32f(v.w);
    }
    reinterpret_cast<float4*>(g_xg + (size_t)row * DD)[i] = v;
}

// RN-round weights once (removes per-mma cvt from the GEMM hot loop)
__global__ void k_roundw(const float* __restrict__ src, float* __restrict__ dst) {
    int i = blockIdx.x * blockDim.x + threadIdx.x;
    float4 v = reinterpret_cast<const float4*>(src)[i];
    v.x = tf32f(v.x); v.y = tf32f(v.y); v.z = tf32f(v.z); v.w = tf32f(v.w);
    reinterpret_cast<float4*>(dst)[i] = v;
}

// ---------------- grouped GEMM (mma.sync m16n8k8 tf32, cp.async double-buffer) ----------
// FUSED=true : A=g_xg [M,1024], B1=w1r, B3=w3r; C=g_h (silu(G)*U, tf32)
// FUSED=false: A=g_h  [M,3584], B1=w2r;         C=g_y (raw fp32)
template<int KD, bool FUSED>
__global__ void __launch_bounds__(256, 2)
k_gemm(const float* __restrict__ B1g, const float* __restrict__ B3g) {
    constexpr int NB    = FUSED ? 2 : 1;
    constexpr int STAGE = (BM + NB * BN) * PADK;   // floats per stage
    constexpr int NK    = KD / BK;
    constexpr int NROWS = FUSED ? FFD : DD;

    extern __shared__ float smem[];

    int m0 = blockIdx.y * BM;
    if (m0 >= g_poff[EE]) return;
    int e = 0;
#pragma unroll
    for (int i = 1; i < EE; i++) if (m0 >= g_poff[i]) e = i;

    int n0 = blockIdx.x * BN;
    const float* Ap  = (FUSED ? g_xg : g_h) + (size_t)m0 * KD;
    const float* B1p = B1g + ((size_t)e * NROWS + n0) * KD;
    const float* B3p = FUSED ? (B3g + ((size_t)e * FFD + n0) * KD) : nullptr;

    uint32_t sbase = (uint32_t)__cvta_generic_to_shared(smem);
    int tid = threadIdx.x;

    auto load_stage = [&](int kt, int buf) {
        uint32_t sb = sbase + (uint32_t)buf * STAGE * 4;
        int k0 = kt * BK;
#pragma unroll
        for (int c = 0; c < 4; c++) {               // A: 128x32 = 1024 x 16B chunks
            int ch = tid + c * 256;
            int row = ch >> 3, kc = (ch & 7) * 4;
            cp16(sb + (uint32_t)(row * PADK + kc) * 4, Ap + (size_t)row * KD + k0 + kc);
        }
#pragma unroll
        for (int c = 0; c < 2; c++) {               // each B: 64x32 = 512 x 16B chunks
            int ch = tid + c * 256;
            int row = ch >> 3, kc = (ch & 7) * 4;
            cp16(sb + (uint32_t)(BM * PADK + row * PADK + kc) * 4,
                 B1p + (size_t)row * KD + k0 + kc);
            if (FUSED)
                cp16(sb + (uint32_t)((BM + BN) * PADK + row * PADK + kc) * 4,
                     B3p + (size_t)row * KD + k0 + kc);
        }
        cp_commit();
    };

    int warp = tid >> 5, lane = tid & 31;
    int wm = warp >> 1, wn = warp & 1;   // 4x2 warp grid, warp tile 32x32
    int g = lane >> 2, tg = lane & 3;

    float accG[2][4][4];
    float accU[2][4][4];
#pragma unroll
    for (int i = 0; i < 2; i++)
#pragma unroll
        for (int j = 0; j < 4; j++)
#pragma unroll
            for (int l = 0; l < 4; l++) {
                accG[i][j][l] = 0.f;
                if (FUSED) accU[i][j][l] = 0.f;
            }

    load_stage(0, 0);
    for (int kt = 0; kt < NK; ++kt) {
        if (kt + 1 < NK) {
            load_stage(kt + 1, (kt + 1) & 1);
            asm volatile("cp.async.wait_group 1;" ::: "memory");
        } else {
            asm volatile("cp.async.wait_group 0;" ::: "memory");
        }
        __syncthreads();

        const float* s   = smem + (kt & 1) * STAGE;
        const float* sA  = s;
        const float* sB1 = s + BM * PADK;
        const float* sB3 = sB1 + BN * PADK;

#pragma unroll
        for (int ks = 0; ks < BK / 8; ks++) {
            int kk = ks * 8;
            uint32_t a[2][4];
#pragma unroll
            for (int i = 0; i < 2; i++) {
                int r = wm * 32 + i * 16 + g;
                a[i][0] = __float_as_uint(sA[r * PADK + kk + tg]);        // pre-rounded
                a[i][1] = __float_as_uint(sA[(r + 8) * PADK + kk + tg]);
                a[i][2] = __float_as_uint(sA[r * PADK + kk + tg + 4]);
                a[i][3] = __float_as_uint(sA[(r + 8) * PADK + kk + tg + 4]);
            }
#pragma unroll
            for (int j = 0; j < 4; j++) {
                int n = wn * 32 + j * 8 + g;
                uint32_t b1[2];
                b1[0] = __float_as_uint(sB1[n * PADK + kk + tg]);         // pre-rounded
                b1[1] = __float_as_uint(sB1[n * PADK + kk + tg + 4]);
                mma8(accG[0][j], a[0], b1);
                mma8(accG[1][j], a[1], b1);
                if (FUSED) {
                    uint32_t b3[2];
                    b3[0] = __float_as_uint(sB3[n * PADK + kk + tg]);
                    b3[1] = __float_as_uint(sB3[n * PADK + kk + tg + 4]);
                    mma8(accU[0][j], a[0], b3);
                    mma8(accU[1][j], a[1], b3);
                }
            }
        }
        __syncthreads();
    }

    // epilogue
#pragma unroll
    for (int i = 0; i < 2; i++) {
        int r = m0 + wm * 32 + i * 16 + g;
#pragma unroll
        for (int j = 0; j < 4; j++) {
            int c = n0 + wn * 32 + j * 8 + 2 * tg;
            if (FUSED) {
                float h0 = silu_mul(accG[i][j][0], accU[i][j][0]);
                float h1 = silu_mul(accG[i][j][1], accU[i][j][1]);
                float h2 = silu_mul(accG[i][j][2], accU[i][j][2]);
                float h3 = silu_mul(accG[i][j][3], accU[i][j][3]);
                *reinterpret_cast<float2*>(g_h + (size_t)r * FFD + c) =
                    make_float2(tf32f(h0), tf32f(h1));
                *reinterpret_cast<float2*>(g_h + (size_t)(r + 8) * FFD + c) =
                    make_float2(tf32f(h2), tf32f(h3));
            } else {
                *reinterpret_cast<float2*>(g_y + (size_t)r * DD + c) =
                    make_float2(accG[i][j][0], accG[i][j][1]);
                *reinterpret_cast<float2*>(g_y + (size_t)(r + 8) * DD + c) =
                    make_float2(accG[i][j][2], accG[i][j][3]);
            }
        }
    }
}

// final weighted combine: exactly 2 terms per token -> deterministic
__global__ void k_combine(float* __restrict__ out) {
    int t = blockIdx.x;
    int s0 = g_slot[2 * t], s1 = g_slot[2 * t + 1];
    float w0 = g_rw[2 * t], w1v = g_rw[2 * t + 1];
    int i = threadIdx.x;
    float4 a = reinterpret_cast<const float4*>(g_y + (size_t)s0 * DD)[i];
    float4 b = reinterpret_cast<const float4*>(g_y + (size_t)s1 * DD)[i];
    float4 r;
    r.x = w0 * a.x + w1v * b.x;
    r.y = w0 * a.y + w1v * b.y;
    r.z = w0 * a.z + w1v * b.z;
    r.w = w0 * a.w + w1v * b.w;
    reinterpret_cast<float4*>(out + (size_t)t * DD)[i] = r;
}

// ---------------- launch ----------------
extern "C" void kernel_launch(void* const* d_in, const int* in_sizes, int n_in,
                              void* d_out, int out_size) {
    const float* x      = (const float*)d_in[0];
    const float* w1     = (const float*)d_in[1];
    const float* w3     = (const float*)d_in[2];
    const float* w2     = (const float*)d_in[3];
    const float* logits = (const float*)d_in[4];
    float* out = (float*)d_out;

    constexpr int SMEM1 = NSTAGE * (BM + 2 * BN) * PADK * 4;  // 73728 B -> 2 CTAs/SM
    constexpr int SMEM2 = NSTAGE * (BM + 1 * BN) * PADK * 4;  // 55296 B -> 2 CTAs/SM
    cudaFuncSetAttribute((const void*)k_gemm<DD,  true >,
                         cudaFuncAttributeMaxDynamicSharedMemorySize, SMEM1);
    cudaFuncSetAttribute((const void*)k_gemm<FFD, false>,
                         cudaFuncAttributeMaxDynamicSharedMemorySize, SMEM2);

    float* w1r; cudaGetSymbolAddress((void**)&w1r, g_w1r);
    float* w3r; cudaGetSymbolAddress((void**)&w3r, g_w3r);
    float* w2r; cudaGetSymbolAddress((void**)&w2r, g_w2r);

    k_route  <<<TT / 256, 256>>>(logits);
    k_count  <<<EE, 256>>>();
    k_offsets<<<1, 1>>>();
    k_scatter<<<EE, 256>>>();
    k_gather <<<MPMAX, 256>>>(x);

    constexpr int WELEM4 = EE * FFD * DD / 4;   // 7340032 float4
    k_roundw<<<WELEM4 / 256, 256>>>(w1, w1r);
    k_roundw<<<WELEM4 / 256, 256>>>(w3, w3r);
    k_roundw<<<WELEM4 / 256, 256>>>(w2, w2r);

    k_gemm<DD,  true ><<<dim3(FFD / BN, MTILES), 256, SMEM1>>>(w1r, w3r);
    k_gemm<FFD, false><<<dim3(DD  / BN, MTILES), 256, SMEM2>>>(w2r, nullptr);

    k_combine<<<TT, 256>>>(out);
}

// round 6
// speedup vs baseline: 1.1161x; 1.0258x over previous
#include <cuda_runtime.h>
#include <cstdint>
#include <math.h>

// Problem constants
#define TT   8192
#define DD   1024
#define EE   8
#define FFD  3584

// GEMM tiling
#define BM   128
#define BN   128
#define BK   32
#define PADK 36     // 36-float row stride: 144B, 16B-aligned, conflict-free frag loads
#define NSTAGE 3

#define MPMAX  (2*TT + EE*BM)   // 17408 max padded slot rows
#define MTILES (MPMAX/BM)       // 136

// ---------------- scratch (device globals; no allocation allowed) ----------------
__device__ float g_xg [(size_t)MPMAX * DD];    // gathered tf32-rounded x
__device__ float g_h  [(size_t)MPMAX * FFD];   // silu(G)*U, tf32-rounded
__device__ float g_y  [(size_t)MPMAX * DD];    // per-slot expert output
__device__ float g_w1r[(size_t)EE * FFD * DD]; // RN-rounded weights
__device__ float g_w3r[(size_t)EE * FFD * DD];
__device__ float g_w2r[(size_t)EE * DD * FFD];
__device__ int   g_perm[MPMAX];
__device__ int   g_ridx[TT * 2];
__device__ float g_rw  [TT * 2];
__device__ int   g_slot[TT * 2];
__device__ int   g_cnt [EE];
__device__ int   g_poff[EE + 1];

// ---------------- helpers ----------------
__device__ __forceinline__ uint32_t cvt_tf32_bits(float v) {
    uint32_t r;
    asm("cvt.rna.tf32.f32 %0, %1;" : "=r"(r) : "f"(v));
    return r;
}
__device__ __forceinline__ float tf32f(float v) {
    return __uint_as_float(cvt_tf32_bits(v));
}
__device__ __forceinline__ void cp16(uint32_t saddr, const float* gptr) {
    asm volatile("cp.async.cg.shared.global [%0], [%1], 16;" :: "r"(saddr), "l"(gptr));
}
__device__ __forceinline__ void cp_commit() {
    asm volatile("cp.async.commit_group;" ::: "memory");
}
__device__ __forceinline__ void mma8(float (&d)[4], const uint32_t (&a)[4], const uint32_t (&b)[2]) {
    asm volatile(
        "mma.sync.aligned.m16n8k8.row.col.f32.tf32.tf32.f32 "
        "{%0,%1,%2,%3},{%4,%5,%6,%7},{%8,%9},{%0,%1,%2,%3};"
        : "+f"(d[0]), "+f"(d[1]), "+f"(d[2]), "+f"(d[3])
        : "r"(a[0]), "r"(a[1]), "r"(a[2]), "r"(a[3]), "r"(b[0]), "r"(b[1]));
}
__device__ __forceinline__ float silu_mul(float gv, float uv) {
    return (gv / (1.0f + __expf(-gv))) * uv;
}

// ---------------- routing: softmax-top2 == softmax over the top-2 logits ----------------
__global__ void k_route(const float* __restrict__ logits) {
    int t = blockIdx.x * blockDim.x + threadIdx.x;
    if (t >= TT) return;
    float v[EE];
#pragma unroll
    for (int e = 0; e < EE; e++) v[e] = logits[t * EE + e];
    int i0 = 0; float b0 = v[0];
#pragma unroll
    for (int e = 1; e < EE; e++) if (v[e] > b0) { b0 = v[e]; i0 = e; }
    int i1 = -1; float b1 = -INFINITY;
#pragma unroll
    for (int e = 0; e < EE; e++) if (e != i0 && v[e] > b1) { b1 = v[e]; i1 = e; }
    float w0 = 1.0f / (1.0f + __expf(b1 - b0));
    g_ridx[2 * t] = i0;  g_ridx[2 * t + 1] = i1;
    g_rw  [2 * t] = w0;  g_rw  [2 * t + 1] = 1.0f - w0;
}

__global__ void k_count() {
    int e = blockIdx.x, tid = threadIdx.x;
    __shared__ int red[256];
    int s = 0;
    for (int t = tid; t < TT; t += 256)
        s += (g_ridx[2 * t] == e) + (g_ridx[2 * t + 1] == e);
    red[tid] = s; __syncthreads();
    for (int o = 128; o > 0; o >>= 1) {
        if (tid < o) red[tid] += red[tid + o];
        __syncthreads();
    }
    if (tid == 0) g_cnt[e] = red[0];
}

__global__ void k_offsets() {
    int acc = 0;
    g_poff[0] = 0;
    for (int e = 0; e < EE; e++) {
        acc += ((g_cnt[e] + BM - 1) / BM) * BM;
        g_poff[e + 1] = acc;
    }
}

// stable (token-order) scatter; deterministic
__global__ void k_scatter() {
    int e = blockIdx.x, tid = threadIdx.x;
    __shared__ int s[256];
    __shared__ int base;
    if (tid == 0) base = 0;
    __syncthreads();
    int off = g_poff[e];
    for (int b = 0; b < TT; b += 256) {
        int t = b + tid;
        int which = -1;
        if (g_ridx[2 * t] == e) which = 0;
        else if (g_ridx[2 * t + 1] == e) which = 1;
        int act = (which >= 0) ? 1 : 0;
        s[tid] = act; __syncthreads();
        for (int o = 1; o < 256; o <<= 1) {
            int v = (tid >= o) ? s[tid - o] : 0;
            __syncthreads();
            s[tid] += v;
            __syncthreads();
        }
        if (act) {
            int pos = base + s[tid] - 1;
            g_perm[off + pos] = t;
            g_slot[2 * t + which] = off + pos;
        }
        __syncthreads();
        if (tid == 0) base += s[255];
        __syncthreads();
    }
    int cnt = g_cnt[e];
    for (int p = off + cnt + tid; p < g_poff[e + 1]; p += 256) g_perm[p] = -1;
}

// gather x rows into slot order, RN-rounded to tf32
__global__ void k_gather(const float* __restrict__ x) {
    int row = blockIdx.x;
    if (row >= g_poff[EE]) return;
    int t = g_perm[row];
    int i = threadIdx.x;
    float4 v = make_float4(0.f, 0.f, 0.f, 0.f);
    if (t >= 0) {
        v = reinterpret_cast<const float4*>(x + (size_t)t * DD)[i];
        v.x = tf32f(v.x); v.y = tf32f(v.y); v.z = tf32f(v.z); v.w = tf32f(v.w);
    }
    reinterpret_cast<float4*>(g_xg + (size_t)row * DD)[i] = v;
}

// RN-round weights once (removes per-mma cvt from the GEMM hot loop)
__global__ void k_roundw(const float* __restrict__ src, float* __restrict__ dst) {
    int i = blockIdx.x * blockDim.x + threadIdx.x;
    float4 v = reinterpret_cast<const float4*>(src)[i];
    v.x = tf32f(v.x); v.y = tf32f(v.y); v.z = tf32f(v.z); v.w = tf32f(v.w);
    reinterpret_cast<float4*>(dst)[i] = v;
}

// ---------------- grouped GEMM (mma.sync m16n8k8 tf32) ----------------
// 8 warps as 2x4 grid of 64x32 warp tiles over a 128x128 CTA tile.
// Per ks-step/warp: 16 A-LDS + 16 B-LDS feed 32 MMAs (ratio 1.0).
// Pipeline: 3-stage cp.async, ONE __syncthreads per kt.
// FUSED=true : A=g_xg [M,1024], B1=w1r, B3=w3r; C=g_h (silu(G)*U, tf32)
// FUSED=false: A=g_h  [M,3584], B1=w2r;         C=g_y (raw fp32)
template<int KD, bool FUSED, int MINB>
__global__ void __launch_bounds__(256, MINB)
k_gemm(const float* __restrict__ B1g, const float* __restrict__ B3g) {
    constexpr int NB    = FUSED ? 2 : 1;
    constexpr int STAGE = (BM + NB * BN) * PADK;   // floats per stage
    constexpr int NK    = KD / BK;
    constexpr int NROWS = FUSED ? FFD : DD;

    extern __shared__ float smem[];

    int m0 = blockIdx.y * BM;
    if (m0 >= g_poff[EE]) return;
    int e = 0;
#pragma unroll
    for (int i = 1; i < EE; i++) if (m0 >= g_poff[i]) e = i;

    int n0 = blockIdx.x * BN;
    const float* Ap  = (FUSED ? g_xg : g_h) + (size_t)m0 * KD;
    const float* B1p = B1g + ((size_t)e * NROWS + n0) * KD;
    const float* B3p = FUSED ? (B3g + ((size_t)e * FFD + n0) * KD) : nullptr;

    uint32_t sbase = (uint32_t)__cvta_generic_to_shared(smem);
    int tid = threadIdx.x;

    auto load_stage = [&](int kt, int buf) {
        uint32_t sb = sbase + (uint32_t)buf * STAGE * 4;
        int k0 = kt * BK;
#pragma unroll
        for (int c = 0; c < 4; c++) {               // A: 128x32 = 1024 x 16B chunks
            int ch = tid + c * 256;
            int row = ch >> 3, kc = (ch & 7) * 4;
            cp16(sb + (uint32_t)(row * PADK + kc) * 4, Ap + (size_t)row * KD + k0 + kc);
        }
#pragma unroll
        for (int c = 0; c < 4; c++) {               // B1: 128x32 = 1024 x 16B chunks
            int ch = tid + c * 256;
            int row = ch >> 3, kc = (ch & 7) * 4;
            cp16(sb + (uint32_t)((BM + row) * PADK + kc) * 4,
                 B1p + (size_t)row * KD + k0 + kc);
        }
        if (FUSED) {
#pragma unroll
            for (int c = 0; c < 4; c++) {           // B3: 128x32
                int ch = tid + c * 256;
                int row = ch >> 3, kc = (ch & 7) * 4;
                cp16(sb + (uint32_t)((BM + BN + row) * PADK + kc) * 4,
                     B3p + (size_t)row * KD + k0 + kc);
            }
        }
        cp_commit();
    };

    int warp = tid >> 5, lane = tid & 31;
    int wm = warp >> 2, wn = warp & 3;   // 2x4 warp grid, warp tile 64x32
    int g = lane >> 2, tg = lane & 3;

    float accG[4][4][4];
    float accU[4][4][4];
#pragma unroll
    for (int i = 0; i < 4; i++)
#pragma unroll
        for (int j = 0; j < 4; j++)
#pragma unroll
            for (int l = 0; l < 4; l++) {
                accG[i][j][l] = 0.f;
                if (FUSED) accU[i][j][l] = 0.f;
            }

    // prologue: fill 2 stages
    load_stage(0, 0);
    load_stage(1, 1);

    int buf = 0;
    for (int kt = 0; kt < NK; ++kt) {
        // wait for stage kt's data (the next stage may still be in flight)
        if (kt < NK - 1) { asm volatile("cp.async.wait_group 1;" ::: "memory"); }
        else             { asm volatile("cp.async.wait_group 0;" ::: "memory"); }
        __syncthreads();   // single barrier per kt: also separates compute(kt-1) readers
                           // of buffer (kt+2)%3 from the load below that overwrites it

        if (kt + 2 < NK) load_stage(kt + 2, (buf + 2) % NSTAGE);

        const float* s   = smem + buf * STAGE;
        const float* sA  = s;
        const float* sB1 = s + BM * PADK;
        const float* sB3 = sB1 + BN * PADK;

#pragma unroll
        for (int ks = 0; ks < BK / 8; ks++) {
            int kk = ks * 8;
            uint32_t a[4][4];
#pragma unroll
            for (int i = 0; i < 4; i++) {
                int r = wm * 64 + i * 16 + g;
                a[i][0] = __float_as_uint(sA[r * PADK + kk + tg]);
                a[i][1] = __float_as_uint(sA[(r + 8) * PADK + kk + tg]);
                a[i][2] = __float_as_uint(sA[r * PADK + kk + tg + 4]);
                a[i][3] = __float_as_uint(sA[(r + 8) * PADK + kk + tg + 4]);
            }
#pragma unroll
            for (int j = 0; j < 4; j++) {
                int n = wn * 32 + j * 8 + g;
                uint32_t b1[2];
                b1[0] = __float_as_uint(sB1[n * PADK + kk + tg]);
                b1[1] = __float_as_uint(sB1[n * PADK + kk + tg + 4]);
#pragma unroll
                for (int i = 0; i < 4; i++) mma8(accG[i][j], a[i], b1);
                if (FUSED) {
                    uint32_t b3[2];
                    b3[0] = __float_as_uint(sB3[n * PADK + kk + tg]);
                    b3[1] = __float_as_uint(sB3[n * PADK + kk + tg + 4]);
#pragma unroll
                    for (int i = 0; i < 4; i++) mma8(accU[i][j], a[i], b3);
                }
            }
        }
        buf = (buf + 1) % NSTAGE;
    }

    // epilogue
#pragma unroll
    for (int i = 0; i < 4; i++) {
        int r = m0 + wm * 64 + i * 16 + g;
#pragma unroll
        for (int j = 0; j < 4; j++) {
            int c = n0 + wn * 32 + j * 8 + 2 * tg;
            if (FUSED) {
                float h0 = silu_mul(accG[i][j][0], accU[i][j][0]);
                float h1 = silu_mul(accG[i][j][1], accU[i][j][1]);
                float h2 = silu_mul(accG[i][j][2], accU[i][j][2]);
                float h3 = silu_mul(accG[i][j][3], accU[i][j][3]);
                *reinterpret_cast<float2*>(g_h + (size_t)r * FFD + c) =
                    make_float2(tf32f(h0), tf32f(h1));
                *reinterpret_cast<float2*>(g_h + (size_t)(r + 8) * FFD + c) =
                    make_float2(tf32f(h2), tf32f(h3));
            } else {
                *reinterpret_cast<float2*>(g_y + (size_t)r * DD + c) =
                    make_float2(accG[i][j][0], accG[i][j][1]);
                *reinterpret_cast<float2*>(g_y + (size_t)(r + 8) * DD + c) =
                    make_float2(accG[i][j][2], accG[i][j][3]);
            }
        }
    }
}

// final weighted combine: exactly 2 terms per token -> deterministic
__global__ void k_combine(float* __restrict__ out) {
    int t = blockIdx.x;
    int s0 = g_slot[2 * t], s1 = g_slot[2 * t + 1];
    float w0 = g_rw[2 * t], w1v = g_rw[2 * t + 1];
    int i = threadIdx.x;
    float4 a = reinterpret_cast<const float4*>(g_y + (size_t)s0 * DD)[i];
    float4 b = reinterpret_cast<const float4*>(g_y + (size_t)s1 * DD)[i];
    float4 r;
    r.x = w0 * a.x + w1v * b.x;
    r.y = w0 * a.y + w1v * b.y;
    r.z = w0 * a.z + w1v * b.z;
    r.w = w0 * a.w + w1v * b.w;
    reinterpret_cast<float4*>(out + (size_t)t * DD)[i] = r;
}

// ---------------- launch ----------------
extern "C" void kernel_launch(void* const* d_in, const int* in_sizes, int n_in,
                              void* d_out, int out_size) {
    const float* x      = (const float*)d_in[0];
    const float* w1     = (const float*)d_in[1];
    const float* w3     = (const float*)d_in[2];
    const float* w2     = (const float*)d_in[3];
    const float* logits = (const float*)d_in[4];
    float* out = (float*)d_out;

    constexpr int SMEM1 = NSTAGE * (BM + 2 * BN) * PADK * 4;  // 165888 B (1 CTA/SM)
    constexpr int SMEM2 = NSTAGE * (BM + 1 * BN) * PADK * 4;  // 110592 B (2 CTAs/SM)
    cudaFuncSetAttribute((const void*)k_gemm<DD,  true,  1>,
                         cudaFuncAttributeMaxDynamicSharedMemorySize, SMEM1);
    cudaFuncSetAttribute((const void*)k_gemm<FFD, false, 2>,
                         cudaFuncAttributeMaxDynamicSharedMemorySize, SMEM2);

    float* w1r; cudaGetSymbolAddress((void**)&w1r, g_w1r);
    float* w3r; cudaGetSymbolAddress((void**)&w3r, g_w3r);
    float* w2r; cudaGetSymbolAddress((void**)&w2r, g_w2r);

    k_route  <<<TT / 256, 256>>>(logits);
    k_count  <<<EE, 256>>>();
    k_offsets<<<1, 1>>>();
    k_scatter<<<EE, 256>>>();
    k_gather <<<MPMAX, 256>>>(x);

    constexpr int WELEM4 = EE * FFD * DD / 4;   // 7340032 float4
    k_roundw<<<WELEM4 / 256, 256>>>(w1, w1r);
    k_roundw<<<WELEM4 / 256, 256>>>(w3, w3r);
    k_roundw<<<WELEM4 / 256, 256>>>(w2, w2r);

    k_gemm<DD,  true,  1><<<dim3(FFD / BN, MTILES), 256, SMEM1>>>(w1r, w3r);
    k_gemm<FFD, false, 2><<<dim3(DD  / BN, MTILES), 256, SMEM2>>>(w2r, nullptr);

    k_combine<<<TT, 256>>>(out);
}

// round 7
// speedup vs baseline: 2.0144x; 1.8048x over previous
#include <cuda_runtime.h>
#include <cuda_fp16.h>
#include <cstdint>
#include <math.h>

// Problem constants
#define TT   8192
#define DD   1024
#define EE   8
#define FFD  3584

// GEMM tiling (fp16 mma.sync m16n8k16)
#define BM   128
#define BN   128
#define BK   64     // halves per stage-K: 64 x 2B = 128B per row
#define PADK 72     // 72-half row stride: 144B, conflict-free frag loads
#define NSTAGE 3

#define MPMAX  (2*TT + EE*BM)   // 17408 max padded slot rows
#define MTILES (MPMAX/BM)       // 136

// ---------------- scratch (device globals; no allocation allowed) ----------------
__device__ __half g_xh [(size_t)MPMAX * DD];    // gathered fp16 x
__device__ __half g_h  [(size_t)MPMAX * FFD];   // silu(G)*U, fp16
__device__ float  g_y  [(size_t)MPMAX * DD];    // per-slot expert output (fp32)
__device__ __half g_w1h[(size_t)EE * FFD * DD]; // fp16 weights
__device__ __half g_w3h[(size_t)EE * FFD * DD];
__device__ __half g_w2h[(size_t)EE * DD * FFD];
__device__ int    g_perm[MPMAX];
__device__ int    g_ridx[TT * 2];
__device__ float  g_rw  [TT * 2];
__device__ int    g_slot[TT * 2];
__device__ int    g_cnt [EE];
__device__ int    g_poff[EE + 1];

// ---------------- helpers ----------------
__device__ __forceinline__ void cp16(uint32_t saddr, const void* gptr) {
    asm volatile("cp.async.cg.shared.global [%0], [%1], 16;" :: "r"(saddr), "l"(gptr));
}
__device__ __forceinline__ void cp_commit() {
    asm volatile("cp.async.commit_group;" ::: "memory");
}
__device__ __forceinline__ void mma16(float (&d)[4], const uint32_t (&a)[4], const uint32_t (&b)[2]) {
    asm volatile(
        "mma.sync.aligned.m16n8k16.row.col.f32.f16.f16.f32 "
        "{%0,%1,%2,%3},{%4,%5,%6,%7},{%8,%9},{%0,%1,%2,%3};"
        : "+f"(d[0]), "+f"(d[1]), "+f"(d[2]), "+f"(d[3])
        : "r"(a[0]), "r"(a[1]), "r"(a[2]), "r"(a[3]), "r"(b[0]), "r"(b[1]));
}
__device__ __forceinline__ float silu_mul(float gv, float uv) {
    return (gv / (1.0f + __expf(-gv))) * uv;
}
__device__ __forceinline__ uint32_t pack_h2(float a, float b) {
    __half2 h = __floats2half2_rn(a, b);
    return *reinterpret_cast<uint32_t*>(&h);
}

// ---------------- routing: softmax-top2 == softmax over the top-2 logits ----------------
__global__ void k_route(const float* __restrict__ logits) {
    int t = blockIdx.x * blockDim.x + threadIdx.x;
    if (t >= TT) return;
    float v[EE];
#pragma unroll
    for (int e = 0; e < EE; e++) v[e] = logits[t * EE + e];
    int i0 = 0; float b0 = v[0];
#pragma unroll
    for (int e = 1; e < EE; e++) if (v[e] > b0) { b0 = v[e]; i0 = e; }
    int i1 = -1; float b1 = -INFINITY;
#pragma unroll
    for (int e = 0; e < EE; e++) if (e != i0 && v[e] > b1) { b1 = v[e]; i1 = e; }
    float w0 = 1.0f / (1.0f + __expf(b1 - b0));
    g_ridx[2 * t] = i0;  g_ridx[2 * t + 1] = i1;
    g_rw  [2 * t] = w0;  g_rw  [2 * t + 1] = 1.0f - w0;
}

__global__ void k_count() {
    int e = blockIdx.x, tid = threadIdx.x;
    __shared__ int red[256];
    int s = 0;
    for (int t = tid; t < TT; t += 256)
        s += (g_ridx[2 * t] == e) + (g_ridx[2 * t + 1] == e);
    red[tid] = s; __syncthreads();
    for (int o = 128; o > 0; o >>= 1) {
        if (tid < o) red[tid] += red[tid + o];
        __syncthreads();
    }
    if (tid == 0) g_cnt[e] = red[0];
}

__global__ void k_offsets() {
    int acc = 0;
    g_poff[0] = 0;
    for (int e = 0; e < EE; e++) {
        acc += ((g_cnt[e] + BM - 1) / BM) * BM;
        g_poff[e + 1] = acc;
    }
}

// stable (token-order) scatter; deterministic
__global__ void k_scatter() {
    int e = blockIdx.x, tid = threadIdx.x;
    __shared__ int s[256];
    __shared__ int base;
    if (tid == 0) base = 0;
    __syncthreads();
    int off = g_poff[e];
    for (int b = 0; b < TT; b += 256) {
        int t = b + tid;
        int which = -1;
        if (g_ridx[2 * t] == e) which = 0;
        else if (g_ridx[2 * t + 1] == e) which = 1;
        int act = (which >= 0) ? 1 : 0;
        s[tid] = act; __syncthreads();
        for (int o = 1; o < 256; o <<= 1) {
            int v = (tid >= o) ? s[tid - o] : 0;
            __syncthreads();
            s[tid] += v;
            __syncthreads();
        }
        if (act) {
            int pos = base + s[tid] - 1;
            g_perm[off + pos] = t;
            g_slot[2 * t + which] = off + pos;
        }
        __syncthreads();
        if (tid == 0) base += s[255];
        __syncthreads();
    }
    int cnt = g_cnt[e];
    for (int p = off + cnt + tid; p < g_poff[e + 1]; p += 256) g_perm[p] = -1;
}

// gather x rows into slot order, RN-converted to fp16
__global__ void k_gather(const float* __restrict__ x) {
    int row = blockIdx.x;
    if (row >= g_poff[EE]) return;
    int t = g_perm[row];
    int i = threadIdx.x;                     // 256 threads x 4 elems = 1024
    float4 v = make_float4(0.f, 0.f, 0.f, 0.f);
    if (t >= 0) v = reinterpret_cast<const float4*>(x + (size_t)t * DD)[i];
    uint2 p;
    p.x = pack_h2(v.x, v.y);
    p.y = pack_h2(v.z, v.w);
    reinterpret_cast<uint2*>(g_xh + (size_t)row * DD)[i] = p;
}

// convert weights fp32 -> fp16 (RN) once
__global__ void k_halfw(const float* __restrict__ src, __half* __restrict__ dst) {
    int i = blockIdx.x * blockDim.x + threadIdx.x;
    float4 v = reinterpret_cast<const float4*>(src)[i];
    uint2 p;
    p.x = pack_h2(v.x, v.y);
    p.y = pack_h2(v.z, v.w);
    reinterpret_cast<uint2*>(dst)[i] = p;
}

// ---------------- grouped GEMM (mma.sync m16n8k16 fp16, fp32 accumulate) ----------------
// 8 warps as 2x4 grid of 64x32 warp tiles over a 128x128 CTA tile.
// 3-stage cp.async pipeline, ONE __syncthreads per kt.
// FUSED=true : A=g_xh [M,1024], B1=w1h, B3=w3h; C=g_h (fp16 silu(G)*U)
// FUSED=false: A=g_h  [M,3584], B1=w2h;         C=g_y (fp32)
template<int KD, bool FUSED, int MINB>
__global__ void __launch_bounds__(256, MINB)
k_gemm(const __half* __restrict__ B1g, const __half* __restrict__ B3g) {
    constexpr int NB    = FUSED ? 2 : 1;
    constexpr int STAGE = (BM + NB * BN) * PADK;   // halves per stage
    constexpr int NK    = KD / BK;
    constexpr int NROWS = FUSED ? FFD : DD;

    extern __shared__ __half smem[];

    int m0 = blockIdx.y * BM;
    if (m0 >= g_poff[EE]) return;
    int e = 0;
#pragma unroll
    for (int i = 1; i < EE; i++) if (m0 >= g_poff[i]) e = i;

    int n0 = blockIdx.x * BN;
    const __half* Ap  = (FUSED ? g_xh : g_h) + (size_t)m0 * KD;
    const __half* B1p = B1g + ((size_t)e * NROWS + n0) * KD;
    const __half* B3p = FUSED ? (B3g + ((size_t)e * FFD + n0) * KD) : nullptr;

    uint32_t sbase = (uint32_t)__cvta_generic_to_shared(smem);
    int tid = threadIdx.x;

    auto load_stage = [&](int kt, int buf) {
        uint32_t sb = sbase + (uint32_t)buf * STAGE * 2;
        int k0 = kt * BK;
#pragma unroll
        for (int c = 0; c < 4; c++) {               // A: 128 rows x 8 chunks (16B = 8 halves)
            int ch = tid + c * 256;
            int row = ch >> 3, kc = (ch & 7) * 8;
            cp16(sb + (uint32_t)(row * PADK + kc) * 2, Ap + (size_t)row * KD + k0 + kc);
        }
#pragma unroll
        for (int c = 0; c < 4; c++) {               // B1: 128 rows x 8 chunks
            int ch = tid + c * 256;
            int row = ch >> 3, kc = (ch & 7) * 8;
            cp16(sb + (uint32_t)((BM + row) * PADK + kc) * 2,
                 B1p + (size_t)row * KD + k0 + kc);
        }
        if (FUSED) {
#pragma unroll
            for (int c = 0; c < 4; c++) {           // B3
                int ch = tid + c * 256;
                int row = ch >> 3, kc = (ch & 7) * 8;
                cp16(sb + (uint32_t)((BM + BN + row) * PADK + kc) * 2,
                     B3p + (size_t)row * KD + k0 + kc);
            }
        }
        cp_commit();
    };

    int warp = tid >> 5, lane = tid & 31;
    int wm = warp >> 2, wn = warp & 3;   // 2x4 warp grid, warp tile 64x32
    int g = lane >> 2, tg = lane & 3;

    float accG[4][4][4];
    float accU[4][4][4];
#pragma unroll
    for (int i = 0; i < 4; i++)
#pragma unroll
        for (int j = 0; j < 4; j++)
#pragma unroll
            for (int l = 0; l < 4; l++) {
                accG[i][j][l] = 0.f;
                if (FUSED) accU[i][j][l] = 0.f;
            }

    load_stage(0, 0);
    load_stage(1, 1);

    int buf = 0;
    for (int kt = 0; kt < NK; ++kt) {
        if (kt < NK - 1) { asm volatile("cp.async.wait_group 1;" ::: "memory"); }
        else             { asm volatile("cp.async.wait_group 0;" ::: "memory"); }
        __syncthreads();   // single barrier per kt; also protects buffer (kt+2)%3 reload

        if (kt + 2 < NK) load_stage(kt + 2, (buf + 2) % NSTAGE);

        const __half* s   = smem + (size_t)buf * STAGE;
        const __half* sA  = s;
        const __half* sB1 = s + BM * PADK;
        const __half* sB3 = sB1 + BN * PADK;

#pragma unroll
        for (int ks = 0; ks < BK / 16; ks++) {       // k16 per mma
            int kk = ks * 16;
            uint32_t a[4][4];
#pragma unroll
            for (int i = 0; i < 4; i++) {
                int r = wm * 64 + i * 16 + g;
                a[i][0] = *reinterpret_cast<const uint32_t*>(sA + r * PADK + kk + 2 * tg);
                a[i][1] = *reinterpret_cast<const uint32_t*>(sA + (r + 8) * PADK + kk + 2 * tg);
                a[i][2] = *reinterpret_cast<const uint32_t*>(sA + r * PADK + kk + 8 + 2 * tg);
                a[i][3] = *reinterpret_cast<const uint32_t*>(sA + (r + 8) * PADK + kk + 8 + 2 * tg);
            }
#pragma unroll
            for (int j = 0; j < 4; j++) {
                int n = wn * 32 + j * 8 + g;
                uint32_t b1[2];
                b1[0] = *reinterpret_cast<const uint32_t*>(sB1 + n * PADK + kk + 2 * tg);
                b1[1] = *reinterpret_cast<const uint32_t*>(sB1 + n * PADK + kk + 8 + 2 * tg);
#pragma unroll
                for (int i = 0; i < 4; i++) mma16(accG[i][j], a[i], b1);
                if (FUSED) {
                    uint32_t b3[2];
                    b3[0] = *reinterpret_cast<const uint32_t*>(sB3 + n * PADK + kk + 2 * tg);
                    b3[1] = *reinterpret_cast<const uint32_t*>(sB3 + n * PADK + kk + 8 + 2 * tg);
#pragma unroll
                    for (int i = 0; i < 4; i++) mma16(accU[i][j], a[i], b3);
                }
            }
        }
        buf = (buf + 1) % NSTAGE;
    }

    // epilogue
#pragma unroll
    for (int i = 0; i < 4; i++) {
        int r = m0 + wm * 64 + i * 16 + g;
#pragma unroll
        for (int j = 0; j < 4; j++) {
            int c = n0 + wn * 32 + j * 8 + 2 * tg;
            if (FUSED) {
                float h0 = silu_mul(accG[i][j][0], accU[i][j][0]);
                float h1 = silu_mul(accG[i][j][1], accU[i][j][1]);
                float h2 = silu_mul(accG[i][j][2], accU[i][j][2]);
                float h3 = silu_mul(accG[i][j][3], accU[i][j][3]);
                *reinterpret_cast<uint32_t*>(g_h + (size_t)r * FFD + c)       = pack_h2(h0, h1);
                *reinterpret_cast<uint32_t*>(g_h + (size_t)(r + 8) * FFD + c) = pack_h2(h2, h3);
            } else {
                *reinterpret_cast<float2*>(g_y + (size_t)r * DD + c) =
                    make_float2(accG[i][j][0], accG[i][j][1]);
                *reinterpret_cast<float2*>(g_y + (size_t)(r + 8) * DD + c) =
                    make_float2(accG[i][j][2], accG[i][j][3]);
            }
        }
    }
}

// final weighted combine: exactly 2 terms per token -> deterministic
__global__ void k_combine(float* __restrict__ out) {
    int t = blockIdx.x;
    int s0 = g_slot[2 * t], s1 = g_slot[2 * t + 1];
    float w0 = g_rw[2 * t], w1v = g_rw[2 * t + 1];
    int i = threadIdx.x;
    float4 a = reinterpret_cast<const float4*>(g_y + (size_t)s0 * DD)[i];
    float4 b = reinterpret_cast<const float4*>(g_y + (size_t)s1 * DD)[i];
    float4 r;
    r.x = w0 * a.x + w1v * b.x;
    r.y = w0 * a.y + w1v * b.y;
    r.z = w0 * a.z + w1v * b.z;
    r.w = w0 * a.w + w1v * b.w;
    reinterpret_cast<float4*>(out + (size_t)t * DD)[i] = r;
}

// ---------------- launch ----------------
extern "C" void kernel_launch(void* const* d_in, const int* in_sizes, int n_in,
                              void* d_out, int out_size) {
    const float* x      = (const float*)d_in[0];
    const float* w1     = (const float*)d_in[1];
    const float* w3     = (const float*)d_in[2];
    const float* w2     = (const float*)d_in[3];
    const float* logits = (const float*)d_in[4];
    float* out = (float*)d_out;

    constexpr int SMEM1 = NSTAGE * (BM + 2 * BN) * PADK * 2;  // 165888 B (1 CTA/SM)
    constexpr int SMEM2 = NSTAGE * (BM + 1 * BN) * PADK * 2;  //  110592 B (2 CTAs/SM)
    cudaFuncSetAttribute((const void*)k_gemm<DD,  true,  1>,
                         cudaFuncAttributeMaxDynamicSharedMemorySize, SMEM1);
    cudaFuncSetAttribute((const void*)k_gemm<FFD, false, 2>,
                         cudaFuncAttributeMaxDynamicSharedMemorySize, SMEM2);

    __half* w1h; cudaGetSymbolAddress((void**)&w1h, g_w1h);
    __half* w3h; cudaGetSymbolAddress((void**)&w3h, g_w3h);
    __half* w2h; cudaGetSymbolAddress((void**)&w2h, g_w2h);

    k_route  <<<TT / 256, 256>>>(logits);
    k_count  <<<EE, 256>>>();
    k_offsets<<<1, 1>>>();
    k_scatter<<<EE, 256>>>();
    k_gather <<<MPMAX, 256>>>(x);

    constexpr int WELEM4 = EE * FFD * DD / 4;   // 7340032 float4 groups
    k_halfw<<<WELEM4 / 256, 256>>>(w1, w1h);
    k_halfw<<<WELEM4 / 256, 256>>>(w3, w3h);
    k_halfw<<<WELEM4 / 256, 256>>>(w2, w2h);

    k_gemm<DD,  true,  1><<<dim3(FFD / BN, MTILES), 256, SMEM1>>>(w1h, w3h);
    k_gemm<FFD, false, 2><<<dim3(DD  / BN, MTILES), 256, SMEM2>>>(w2h, nullptr);

    k_combine<<<TT, 256>>>(out);
}